// round 3
// baseline (speedup 1.0000x reference)
#include <cuda_runtime.h>
#include <math.h>
#include <stdint.h>

// ---------------------------------------------------------------------------
// Problem constants (static per the reference)
// ---------------------------------------------------------------------------
#define S_TOT   13294
#define BATCH   2
#define M_TOTAL (BATCH * S_TOT)     // 26588 tokens
#define DM      256
#define DFF     1024
#define NQP     384                 // 256 offset cols + 128 attn cols

__device__ __constant__ int c_HS[4]    = {100, 50, 25, 13};
__device__ __constant__ int c_WS[4]    = {100, 50, 25, 13};
__device__ __constant__ int c_START[4] = {0, 10000, 12500, 13125};

// ---------------------------------------------------------------------------
// Scratch (no allocations allowed -> __device__ globals)
// ---------------------------------------------------------------------------
__device__ float g_value[(size_t)M_TOTAL * DM];
__device__ float g_qproj[(size_t)M_TOTAL * NQP];
__device__ float g_attn [(size_t)M_TOTAL * DM];
__device__ float g_src2 [(size_t)M_TOTAL * DM];
__device__ float g_x    [(size_t)M_TOTAL * DM];
__device__ float g_hbuf [(size_t)M_TOTAL * DFF];
__device__ float g_fbuf [(size_t)M_TOTAL * DM];
__device__ float g_wcat [DM * NQP];
__device__ float g_bcat [NQP];

// ---------------------------------------------------------------------------
// Concatenate W_off | W_attn into one (256 x 384) weight + bias
// ---------------------------------------------------------------------------
__global__ void concat_kernel(const float* __restrict__ Woff, const float* __restrict__ boff,
                              const float* __restrict__ Wattn, const float* __restrict__ battn)
{
    int idx = blockIdx.x * blockDim.x + threadIdx.x;
    if (idx < DM * NQP) {
        int k = idx / NQP, c = idx - k * NQP;
        g_wcat[idx] = (c < 256) ? Woff[k * 256 + c] : Wattn[k * 128 + (c - 256)];
    }
    if (idx < NQP) {
        g_bcat[idx] = (idx < 256) ? boff[idx] : battn[idx - 256];
    }
}

// ---------------------------------------------------------------------------
// SGEMM: C[M,N] = act(A@W + bias), optional A := A + A2 fused on load.
// BM=BN=128, BK=8, 256 threads, 8x8 per thread, warp-tiled 64x32.
// Double-buffered smem pipeline (one __syncthreads per K-slice).
// N must be a multiple of 128 and K a multiple of 8 (true for all calls).
// ---------------------------------------------------------------------------
template<bool RELU, bool ADD2>
__global__ __launch_bounds__(256, 2)
void sgemm_kernel(const float* __restrict__ A, const float* __restrict__ A2,
                  const float* __restrict__ W, const float* __restrict__ bias,
                  float* __restrict__ C, int M, int N, int K)
{
    __shared__ float As[2][8][128];
    __shared__ float Ws[2][8][128];

    const int bm  = blockIdx.y * 128;
    const int bn  = blockIdx.x * 128;
    const int tid = threadIdx.x;
    const int w    = tid >> 5;
    const int lane = tid & 31;
    // warp tile: 2x4 warps, each warp 64 rows x 32 cols; thread 8x8
    const int tr = ((w & 1) << 6) + ((lane >> 2) << 3);
    const int tc = ((w >> 1) << 5) + ((lane & 3) << 3);

    // load mapping
    const int arow = tid >> 1;            // 0..127
    const int acol = (tid & 1) << 2;      // 0 or 4
    const int wrow = tid >> 5;            // 0..7
    const int wcol = (tid & 31) << 2;     // 0..124

    float acc[8][8];
    #pragma unroll
    for (int i = 0; i < 8; i++)
        #pragma unroll
        for (int j = 0; j < 8; j++) acc[i][j] = 0.f;

    const bool avalid = (bm + arow) < M;
    const float* Aptr  = A  + (size_t)(bm + arow) * K + acol;
    const float* A2ptr = A2 + (size_t)(bm + arow) * K + acol;
    const float* Wptr  = W  + (size_t)wrow * N + bn + wcol;

    const int nk = K >> 3;

    // ---- preload slice 0 into buffer 0 ----
    {
        float4 a4 = make_float4(0.f, 0.f, 0.f, 0.f);
        if (avalid) {
            a4 = *(const float4*)(Aptr);
            if (ADD2) {
                float4 b4 = *(const float4*)(A2ptr);
                a4.x += b4.x; a4.y += b4.y; a4.z += b4.z; a4.w += b4.w;
            }
        }
        As[0][acol + 0][arow] = a4.x;
        As[0][acol + 1][arow] = a4.y;
        As[0][acol + 2][arow] = a4.z;
        As[0][acol + 3][arow] = a4.w;
        *(float4*)&Ws[0][wrow][wcol] = *(const float4*)(Wptr);
    }
    __syncthreads();

    int cur = 0;
    for (int k0 = 1; k0 <= nk; k0++) {
        // issue next-tile global loads early (latency hidden behind FFMAs)
        float4 a4n = make_float4(0.f, 0.f, 0.f, 0.f);
        float4 w4n;
        const bool more = (k0 < nk);
        if (more) {
            if (avalid) {
                a4n = *(const float4*)(Aptr + k0 * 8);
                if (ADD2) {
                    float4 b4 = *(const float4*)(A2ptr + k0 * 8);
                    a4n.x += b4.x; a4n.y += b4.y; a4n.z += b4.z; a4n.w += b4.w;
                }
            }
            w4n = *(const float4*)(Wptr + (size_t)(k0 * 8) * N);
        }

        // compute on current buffer
        #pragma unroll
        for (int kk = 0; kk < 8; kk++) {
            float a[8], b[8];
            *(float4*)&a[0] = *(const float4*)&As[cur][kk][tr];
            *(float4*)&a[4] = *(const float4*)&As[cur][kk][tr + 4];
            *(float4*)&b[0] = *(const float4*)&Ws[cur][kk][tc];
            *(float4*)&b[4] = *(const float4*)&Ws[cur][kk][tc + 4];
            #pragma unroll
            for (int i = 0; i < 8; i++)
                #pragma unroll
                for (int j = 0; j < 8; j++)
                    acc[i][j] += a[i] * b[j];
        }

        if (more) {
            const int nxt = cur ^ 1;
            As[nxt][acol + 0][arow] = a4n.x;
            As[nxt][acol + 1][arow] = a4n.y;
            As[nxt][acol + 2][arow] = a4n.z;
            As[nxt][acol + 3][arow] = a4n.w;
            *(float4*)&Ws[nxt][wrow][wcol] = w4n;
            __syncthreads();
            cur = nxt;
        }
    }

    float bia[8];
    *(float4*)&bia[0] = *(const float4*)(bias + bn + tc);
    *(float4*)&bia[4] = *(const float4*)(bias + bn + tc + 4);

    #pragma unroll
    for (int i = 0; i < 8; i++) {
        int row = bm + tr + i;
        if (row < M) {
            float o[8];
            #pragma unroll
            for (int j = 0; j < 8; j++) {
                o[j] = acc[i][j] + bia[j];
                if (RELU) o[j] = fmaxf(o[j], 0.f);
            }
            *(float4*)(C + (size_t)row * N + bn + tc)     = *(float4*)&o[0];
            *(float4*)(C + (size_t)row * N + bn + tc + 4) = *(float4*)&o[4];
        }
    }
}

// ---------------------------------------------------------------------------
// MS deformable attention sampling.
// grid = M_TOTAL blocks, block = (32, 8): warp per head, lane per channel.
// Reads g_qproj (offsets + attn logits), g_value; writes g_attn.
// ---------------------------------------------------------------------------
__global__ void msda_kernel(const float* __restrict__ refp)
{
    const int m    = blockIdx.x;
    const int h    = threadIdx.y;
    const int lane = threadIdx.x;
    const int n = m / S_TOT;

    const float* qp = g_qproj + (size_t)m * NQP;

    // softmax over the head's 16 logits (redundant per lane; broadcast loads)
    float lg[16];
    float mx = -1e30f;
    #pragma unroll
    for (int i = 0; i < 16; i++) {
        lg[i] = qp[256 + h * 16 + i];
        mx = fmaxf(mx, lg[i]);
    }
    float sum = 0.f;
    #pragma unroll
    for (int i = 0; i < 16; i++) { lg[i] = __expf(lg[i] - mx); sum += lg[i]; }
    const float inv = 1.0f / sum;

    const float* rp = refp + (size_t)m * 8;   // (4 levels, 2)
    float acc = 0.f;

    #pragma unroll
    for (int l = 0; l < 4; l++) {
        const int Hl = c_HS[l], Wl = c_WS[l], st = c_START[l];
        const float rx = rp[l * 2 + 0] * (float)Wl - 0.5f;
        const float ry = rp[l * 2 + 1] * (float)Hl - 0.5f;
        const float* vb = g_value + ((size_t)(n * S_TOT + st)) * DM + h * 32 + lane;

        #pragma unroll
        for (int p = 0; p < 4; p++) {
            const int oc = ((h * 4 + l) * 4 + p) * 2;
            const float x  = rx + qp[oc];
            const float y  = ry + qp[oc + 1];
            const float aw = lg[l * 4 + p] * inv;

            const float xf = floorf(x), yf = floorf(y);
            const int x0 = (int)xf, y0 = (int)yf;
            const float wx1 = x - xf, wy1 = y - yf;
            const float wx0 = 1.f - wx1, wy0 = 1.f - wy1;

            float v = 0.f;
            const int x1 = x0 + 1, y1 = y0 + 1;
            const bool vx0 = (x0 >= 0) & (x0 < Wl);
            const bool vx1 = (x1 >= 0) & (x1 < Wl);
            const bool vy0 = (y0 >= 0) & (y0 < Hl);
            const bool vy1 = (y1 >= 0) & (y1 < Hl);
            if (vy0) {
                const size_t r0 = (size_t)(y0 * Wl) * DM;
                if (vx0) v += __ldg(vb + r0 + (size_t)x0 * DM) * (wy0 * wx0);
                if (vx1) v += __ldg(vb + r0 + (size_t)x1 * DM) * (wy0 * wx1);
            }
            if (vy1) {
                const size_t r1 = (size_t)(y1 * Wl) * DM;
                if (vx0) v += __ldg(vb + r1 + (size_t)x0 * DM) * (wy1 * wx0);
                if (vx1) v += __ldg(vb + r1 + (size_t)x1 * DM) * (wy1 * wx1);
            }
            acc += aw * v;
        }
    }
    g_attn[(size_t)m * DM + h * 32 + lane] = acc;
}

// ---------------------------------------------------------------------------
// LayerNorm(a + b) over 256 cols; warp per row, 8 rows per block.
// ---------------------------------------------------------------------------
__global__ void ln_kernel(const float* __restrict__ a, const float* __restrict__ b,
                          const float* __restrict__ gam, const float* __restrict__ bet,
                          float* __restrict__ out)
{
    const int row = blockIdx.x * blockDim.y + threadIdx.y;
    if (row >= M_TOTAL) return;
    const int lane = threadIdx.x;
    const float* ap = a + (size_t)row * DM;
    const float* bp = b + (size_t)row * DM;

    float v[8];
    float s = 0.f;
    #pragma unroll
    for (int i = 0; i < 8; i++) {
        int c = i * 32 + lane;
        v[i] = ap[c] + bp[c];
        s += v[i];
    }
    #pragma unroll
    for (int o = 16; o > 0; o >>= 1) s += __shfl_xor_sync(0xffffffffu, s, o);
    const float mean = s * (1.0f / 256.0f);

    float var = 0.f;
    #pragma unroll
    for (int i = 0; i < 8; i++) { float d = v[i] - mean; var += d * d; }
    #pragma unroll
    for (int o = 16; o > 0; o >>= 1) var += __shfl_xor_sync(0xffffffffu, var, o);
    var *= (1.0f / 256.0f);
    const float r = rsqrtf(var + 1e-5f);

    float* op = out + (size_t)row * DM;
    #pragma unroll
    for (int i = 0; i < 8; i++) {
        int c = i * 32 + lane;
        op[c] = (v[i] - mean) * r * gam[c] + bet[c];
    }
}

// ---------------------------------------------------------------------------
// Launch
// ---------------------------------------------------------------------------
extern "C" void kernel_launch(void* const* d_in, const int* in_sizes, int n_in,
                              void* d_out, int out_size)
{
    const float* src   = (const float*)d_in[0];
    const float* pos   = (const float*)d_in[1];
    const float* refp  = (const float*)d_in[2];
    // d_in[3] spatial_shapes, d_in[4] level_start_index: static, hardcoded
    const float* W_off = (const float*)d_in[5];
    const float* b_off = (const float*)d_in[6];
    const float* W_att = (const float*)d_in[7];
    const float* b_att = (const float*)d_in[8];
    const float* W_val = (const float*)d_in[9];
    const float* b_val = (const float*)d_in[10];
    const float* W_out = (const float*)d_in[11];
    const float* b_out = (const float*)d_in[12];
    const float* W1    = (const float*)d_in[13];
    const float* b1    = (const float*)d_in[14];
    const float* W2    = (const float*)d_in[15];
    const float* b2    = (const float*)d_in[16];
    const float* g1    = (const float*)d_in[17];
    const float* be1   = (const float*)d_in[18];
    const float* g2    = (const float*)d_in[19];
    const float* be2   = (const float*)d_in[20];

    float *p_value, *p_qproj, *p_attn, *p_src2, *p_x, *p_h, *p_f, *p_wcat, *p_bcat;
    cudaGetSymbolAddress((void**)&p_value, g_value);
    cudaGetSymbolAddress((void**)&p_qproj, g_qproj);
    cudaGetSymbolAddress((void**)&p_attn,  g_attn);
    cudaGetSymbolAddress((void**)&p_src2,  g_src2);
    cudaGetSymbolAddress((void**)&p_x,     g_x);
    cudaGetSymbolAddress((void**)&p_h,     g_hbuf);
    cudaGetSymbolAddress((void**)&p_f,     g_fbuf);
    cudaGetSymbolAddress((void**)&p_wcat,  g_wcat);
    cudaGetSymbolAddress((void**)&p_bcat,  g_bcat);

    const int MB = (M_TOTAL + 127) / 128;   // 208

    // 1) concat offset/attn projection weights
    concat_kernel<<<(DM * NQP + 255) / 256, 256>>>(W_off, b_off, W_att, b_att);

    // 2) value = src @ W_val + b_val
    sgemm_kernel<false, false><<<dim3(DM / 128, MB), 256>>>(
        src, nullptr, W_val, b_val, p_value, M_TOTAL, DM, DM);

    // 3) qproj = (src + pos) @ [W_off|W_attn] + [b_off|b_attn]
    sgemm_kernel<false, true><<<dim3(NQP / 128, MB), 256>>>(
        src, pos, p_wcat, p_bcat, p_qproj, M_TOTAL, NQP, DM);

    // 4) deformable sampling -> g_attn
    msda_kernel<<<M_TOTAL, dim3(32, 8)>>>(refp);

    // 5) src2 = attn @ W_out + b_out
    sgemm_kernel<false, false><<<dim3(DM / 128, MB), 256>>>(
        p_attn, nullptr, W_out, b_out, p_src2, M_TOTAL, DM, DM);

    // 6) x = LN(src + src2)
    ln_kernel<<<(M_TOTAL + 7) / 8, dim3(32, 8)>>>(src, p_src2, g1, be1, p_x);

    // 7) h = relu(x @ W1 + b1)
    sgemm_kernel<true, false><<<dim3(DFF / 128, MB), 256>>>(
        p_x, nullptr, W1, b1, p_h, M_TOTAL, DFF, DM);

    // 8) f = h @ W2 + b2
    sgemm_kernel<false, false><<<dim3(DM / 128, MB), 256>>>(
        p_h, nullptr, W2, b2, p_f, M_TOTAL, DM, DFF);

    // 9) out = LN(x + f)
    ln_kernel<<<(M_TOTAL + 7) / 8, dim3(32, 8)>>>(p_x, p_f, g2, be2, (float*)d_out);
}

// round 6
// speedup vs baseline: 1.2201x; 1.2201x over previous
#include <cuda_runtime.h>
#include <math.h>
#include <stdint.h>

// ---------------------------------------------------------------------------
// Problem constants (static per the reference)
// ---------------------------------------------------------------------------
#define S_TOT   13294
#define BATCH   2
#define M_TOTAL (BATCH * S_TOT)     // 26588 tokens
#define DM      256
#define DFF     1024
#define NQP     384                 // 256 offset cols + 128 attn cols

__device__ __constant__ int c_HS[4]    = {100, 50, 25, 13};
__device__ __constant__ int c_WS[4]    = {100, 50, 25, 13};
__device__ __constant__ int c_START[4] = {0, 10000, 12500, 13125};

// ---------------------------------------------------------------------------
// Scratch (no allocations allowed -> __device__ globals)
// ---------------------------------------------------------------------------
__device__ float g_value[(size_t)M_TOTAL * DM];
__device__ float g_qproj[(size_t)M_TOTAL * NQP];
__device__ float g_attn [(size_t)M_TOTAL * DM];
__device__ float g_src2 [(size_t)M_TOTAL * DM];
__device__ float g_x    [(size_t)M_TOTAL * DM];
__device__ float g_hbuf [(size_t)M_TOTAL * DFF];
__device__ float g_fbuf [(size_t)M_TOTAL * DM];
__device__ float g_wcat [DM * NQP];
__device__ float g_bcat [NQP];

// ---------------------------------------------------------------------------
// Concatenate W_off | W_attn into one (256 x 384) weight + bias
// ---------------------------------------------------------------------------
__global__ void concat_kernel(const float* __restrict__ Woff, const float* __restrict__ boff,
                              const float* __restrict__ Wattn, const float* __restrict__ battn)
{
    int idx = blockIdx.x * blockDim.x + threadIdx.x;
    if (idx < DM * NQP) {
        int k = idx / NQP, c = idx - k * NQP;
        g_wcat[idx] = (c < 256) ? Woff[k * 256 + c] : Wattn[k * 128 + (c - 256)];
    }
    if (idx < NQP) {
        g_bcat[idx] = (idx < 256) ? boff[idx] : battn[idx - 256];
    }
}

// ---------------------------------------------------------------------------
// SGEMM: C[M,N] = act(A@W + bias), optional A := A + A2 fused on load.
// BM=BN=128, BK=8, 256 threads, 8x8 per thread, warp-tiled 64x32.
// Double-buffered smem pipeline (one __syncthreads per K-slice).
// ---------------------------------------------------------------------------
template<bool RELU, bool ADD2>
__global__ __launch_bounds__(256, 2)
void sgemm_kernel(const float* __restrict__ A, const float* __restrict__ A2,
                  const float* __restrict__ W, const float* __restrict__ bias,
                  float* __restrict__ C, int M, int N, int K)
{
    __shared__ float As[2][8][128];
    __shared__ float Ws[2][8][128];

    const int bm  = blockIdx.y * 128;
    const int bn  = blockIdx.x * 128;
    const int tid = threadIdx.x;
    const int w    = tid >> 5;
    const int lane = tid & 31;
    const int tr = ((w & 1) << 6) + ((lane >> 2) << 3);
    const int tc = ((w >> 1) << 5) + ((lane & 3) << 3);

    const int arow = tid >> 1;
    const int acol = (tid & 1) << 2;
    const int wrow = tid >> 5;
    const int wcol = (tid & 31) << 2;

    float acc[8][8];
    #pragma unroll
    for (int i = 0; i < 8; i++)
        #pragma unroll
        for (int j = 0; j < 8; j++) acc[i][j] = 0.f;

    const bool avalid = (bm + arow) < M;
    const float* Aptr  = A  + (size_t)(bm + arow) * K + acol;
    const float* A2ptr = A2 + (size_t)(bm + arow) * K + acol;
    const float* Wptr  = W  + (size_t)wrow * N + bn + wcol;

    const int nk = K >> 3;

    {
        float4 a4 = make_float4(0.f, 0.f, 0.f, 0.f);
        if (avalid) {
            a4 = *(const float4*)(Aptr);
            if (ADD2) {
                float4 b4 = *(const float4*)(A2ptr);
                a4.x += b4.x; a4.y += b4.y; a4.z += b4.z; a4.w += b4.w;
            }
        }
        As[0][acol + 0][arow] = a4.x;
        As[0][acol + 1][arow] = a4.y;
        As[0][acol + 2][arow] = a4.z;
        As[0][acol + 3][arow] = a4.w;
        *(float4*)&Ws[0][wrow][wcol] = *(const float4*)(Wptr);
    }
    __syncthreads();

    int cur = 0;
    for (int k0 = 1; k0 <= nk; k0++) {
        float4 a4n = make_float4(0.f, 0.f, 0.f, 0.f);
        float4 w4n;
        const bool more = (k0 < nk);
        if (more) {
            if (avalid) {
                a4n = *(const float4*)(Aptr + k0 * 8);
                if (ADD2) {
                    float4 b4 = *(const float4*)(A2ptr + k0 * 8);
                    a4n.x += b4.x; a4n.y += b4.y; a4n.z += b4.z; a4n.w += b4.w;
                }
            }
            w4n = *(const float4*)(Wptr + (size_t)(k0 * 8) * N);
        }

        #pragma unroll
        for (int kk = 0; kk < 8; kk++) {
            float a[8], b[8];
            *(float4*)&a[0] = *(const float4*)&As[cur][kk][tr];
            *(float4*)&a[4] = *(const float4*)&As[cur][kk][tr + 4];
            *(float4*)&b[0] = *(const float4*)&Ws[cur][kk][tc];
            *(float4*)&b[4] = *(const float4*)&Ws[cur][kk][tc + 4];
            #pragma unroll
            for (int i = 0; i < 8; i++)
                #pragma unroll
                for (int j = 0; j < 8; j++)
                    acc[i][j] += a[i] * b[j];
        }

        if (more) {
            const int nxt = cur ^ 1;
            As[nxt][acol + 0][arow] = a4n.x;
            As[nxt][acol + 1][arow] = a4n.y;
            As[nxt][acol + 2][arow] = a4n.z;
            As[nxt][acol + 3][arow] = a4n.w;
            *(float4*)&Ws[nxt][wrow][wcol] = w4n;
            __syncthreads();
            cur = nxt;
        }
    }

    float bia[8];
    *(float4*)&bia[0] = *(const float4*)(bias + bn + tc);
    *(float4*)&bia[4] = *(const float4*)(bias + bn + tc + 4);

    #pragma unroll
    for (int i = 0; i < 8; i++) {
        int row = bm + tr + i;
        if (row < M) {
            float o[8];
            #pragma unroll
            for (int j = 0; j < 8; j++) {
                o[j] = acc[i][j] + bia[j];
                if (RELU) o[j] = fmaxf(o[j], 0.f);
            }
            *(float4*)(C + (size_t)row * N + bn + tc)     = *(float4*)&o[0];
            *(float4*)(C + (size_t)row * N + bn + tc + 4) = *(float4*)&o[4];
        }
    }
}

// ---------------------------------------------------------------------------
// MS deformable attention sampling (warp-cooperative).
// grid = M_TOTAL blocks, block = (32, 8): warp per head, lane per channel.
// Phase 1: lanes 0..15 each own one (level, point) -> softmax (16-lane
//          butterfly), bilinear weights premultiplied by attn weight, and
//          corner element-offsets (invalid corner -> weight 0, offset 0).
// Phase 2: all 32 lanes gather 16x4 corners with LDS.128 broadcast scalars.
// ---------------------------------------------------------------------------
__global__ __launch_bounds__(256)
void msda_kernel(const float* __restrict__ refp)
{
    __shared__ float4 s_w[8][16];
    __shared__ int4   s_o[8][16];

    const int m    = blockIdx.x;
    const int h    = threadIdx.y;
    const int lane = threadIdx.x;
    const int n    = m / S_TOT;

    const float* qp = g_qproj + (size_t)m * NQP;

    // --- Phase 1: softmax over this head's 16 logits (lanes 0..15) ---
    float lg = (lane < 16) ? qp[256 + h * 16 + lane] : -1e30f;
    float mx = lg;
    #pragma unroll
    for (int o = 8; o > 0; o >>= 1) mx = fmaxf(mx, __shfl_xor_sync(0xffffffffu, mx, o));
    float e = __expf(lg - mx);
    float s = e;
    #pragma unroll
    for (int o = 8; o > 0; o >>= 1) s += __shfl_xor_sync(0xffffffffu, s, o);
    const float aw = e / s;

    if (lane < 16) {
        const int l  = lane >> 2;          // level
        const int Hl = c_HS[l], Wl = c_WS[l], st = c_START[l];

        const float2 off2 = *(const float2*)(qp + h * 32 + lane * 2);
        const float x = refp[(size_t)m * 8 + l * 2 + 0] * (float)Wl - 0.5f + off2.x;
        const float y = refp[(size_t)m * 8 + l * 2 + 1] * (float)Hl - 0.5f + off2.y;

        const float xf = floorf(x), yf = floorf(y);
        const int x0 = (int)xf, y0 = (int)yf;
        const int x1 = x0 + 1, y1 = y0 + 1;
        const float wx1 = x - xf, wy1 = y - yf;
        const float wx0 = 1.f - wx1, wy0 = 1.f - wy1;

        const bool vx0 = (x0 >= 0) & (x0 < Wl);
        const bool vx1 = (x1 >= 0) & (x1 < Wl);
        const bool vy0 = (y0 >= 0) & (y0 < Hl);
        const bool vy1 = (y1 >= 0) & (y1 < Hl);

        float4 w4;
        int4   o4;
        const bool v00 = vy0 & vx0, v01 = vy0 & vx1, v10 = vy1 & vx0, v11 = vy1 & vx1;
        w4.x = v00 ? wy0 * wx0 * aw : 0.f;
        w4.y = v01 ? wy0 * wx1 * aw : 0.f;
        w4.z = v10 ? wy1 * wx0 * aw : 0.f;
        w4.w = v11 ? wy1 * wx1 * aw : 0.f;
        o4.x = v00 ? (st + y0 * Wl + x0) * DM : 0;
        o4.y = v01 ? (st + y0 * Wl + x1) * DM : 0;
        o4.z = v10 ? (st + y1 * Wl + x0) * DM : 0;
        o4.w = v11 ? (st + y1 * Wl + x1) * DM : 0;

        s_w[h][lane] = w4;
        s_o[h][lane] = o4;
    }
    __syncwarp();

    // --- Phase 2: gather + weighted accumulate (all 32 lanes = channels) ---
    const float* vb = g_value + (size_t)n * S_TOT * DM + h * 32 + lane;
    float acc = 0.f;
    #pragma unroll
    for (int p = 0; p < 16; p++) {
        const float4 w4 = s_w[h][p];
        const int4   o4 = s_o[h][p];
        acc += __ldg(vb + o4.x) * w4.x;
        acc += __ldg(vb + o4.y) * w4.y;
        acc += __ldg(vb + o4.z) * w4.z;
        acc += __ldg(vb + o4.w) * w4.w;
    }
    g_attn[(size_t)m * DM + h * 32 + lane] = acc;
}

// ---------------------------------------------------------------------------
// LayerNorm(a + b) over 256 cols; warp per row, 8 rows per block.
// ---------------------------------------------------------------------------
__global__ void ln_kernel(const float* __restrict__ a, const float* __restrict__ b,
                          const float* __restrict__ gam, const float* __restrict__ bet,
                          float* __restrict__ out)
{
    const int row = blockIdx.x * blockDim.y + threadIdx.y;
    if (row >= M_TOTAL) return;
    const int lane = threadIdx.x;
    const float* ap = a + (size_t)row * DM;
    const float* bp = b + (size_t)row * DM;

    float v[8];
    float s = 0.f;
    #pragma unroll
    for (int i = 0; i < 8; i++) {
        int c = i * 32 + lane;
        v[i] = ap[c] + bp[c];
        s += v[i];
    }
    #pragma unroll
    for (int o = 16; o > 0; o >>= 1) s += __shfl_xor_sync(0xffffffffu, s, o);
    const float mean = s * (1.0f / 256.0f);

    float var = 0.f;
    #pragma unroll
    for (int i = 0; i < 8; i++) { float d = v[i] - mean; var += d * d; }
    #pragma unroll
    for (int o = 16; o > 0; o >>= 1) var += __shfl_xor_sync(0xffffffffu, var, o);
    var *= (1.0f / 256.0f);
    const float r = rsqrtf(var + 1e-5f);

    float* op = out + (size_t)row * DM;
    #pragma unroll
    for (int i = 0; i < 8; i++) {
        int c = i * 32 + lane;
        op[c] = (v[i] - mean) * r * gam[c] + bet[c];
    }
}

// ---------------------------------------------------------------------------
// Launch
// ---------------------------------------------------------------------------
extern "C" void kernel_launch(void* const* d_in, const int* in_sizes, int n_in,
                              void* d_out, int out_size)
{
    const float* src   = (const float*)d_in[0];
    const float* pos   = (const float*)d_in[1];
    const float* refp  = (const float*)d_in[2];
    const float* W_off = (const float*)d_in[5];
    const float* b_off = (const float*)d_in[6];
    const float* W_att = (const float*)d_in[7];
    const float* b_att = (const float*)d_in[8];
    const float* W_val = (const float*)d_in[9];
    const float* b_val = (const float*)d_in[10];
    const float* W_out = (const float*)d_in[11];
    const float* b_out = (const float*)d_in[12];
    const float* W1    = (const float*)d_in[13];
    const float* b1    = (const float*)d_in[14];
    const float* W2    = (const float*)d_in[15];
    const float* b2    = (const float*)d_in[16];
    const float* g1    = (const float*)d_in[17];
    const float* be1   = (const float*)d_in[18];
    const float* g2    = (const float*)d_in[19];
    const float* be2   = (const float*)d_in[20];

    float *p_value, *p_qproj, *p_attn, *p_src2, *p_x, *p_h, *p_f, *p_wcat, *p_bcat;
    cudaGetSymbolAddress((void**)&p_value, g_value);
    cudaGetSymbolAddress((void**)&p_qproj, g_qproj);
    cudaGetSymbolAddress((void**)&p_attn,  g_attn);
    cudaGetSymbolAddress((void**)&p_src2,  g_src2);
    cudaGetSymbolAddress((void**)&p_x,     g_x);
    cudaGetSymbolAddress((void**)&p_h,     g_hbuf);
    cudaGetSymbolAddress((void**)&p_f,     g_fbuf);
    cudaGetSymbolAddress((void**)&p_wcat,  g_wcat);
    cudaGetSymbolAddress((void**)&p_bcat,  g_bcat);

    const int MB = (M_TOTAL + 127) / 128;   // 208

    concat_kernel<<<(DM * NQP + 255) / 256, 256>>>(W_off, b_off, W_att, b_att);

    sgemm_kernel<false, false><<<dim3(DM / 128, MB), 256>>>(
        src, nullptr, W_val, b_val, p_value, M_TOTAL, DM, DM);

    sgemm_kernel<false, true><<<dim3(NQP / 128, MB), 256>>>(
        src, pos, p_wcat, p_bcat, p_qproj, M_TOTAL, NQP, DM);

    msda_kernel<<<M_TOTAL, dim3(32, 8)>>>(refp);

    sgemm_kernel<false, false><<<dim3(DM / 128, MB), 256>>>(
        p_attn, nullptr, W_out, b_out, p_src2, M_TOTAL, DM, DM);

    ln_kernel<<<(M_TOTAL + 7) / 8, dim3(32, 8)>>>(src, p_src2, g1, be1, p_x);

    sgemm_kernel<true, false><<<dim3(DFF / 128, MB), 256>>>(
        p_x, nullptr, W1, b1, p_h, M_TOTAL, DFF, DM);

    sgemm_kernel<false, false><<<dim3(DM / 128, MB), 256>>>(
        p_h, nullptr, W2, b2, p_f, M_TOTAL, DM, DFF);

    ln_kernel<<<(M_TOTAL + 7) / 8, dim3(32, 8)>>>(p_x, p_f, g2, be2, (float*)d_out);
}

// round 10
// speedup vs baseline: 1.2542x; 1.0279x over previous
#include <cuda_runtime.h>
#include <math.h>
#include <stdint.h>

// ---------------------------------------------------------------------------
// Problem constants (static per the reference)
// ---------------------------------------------------------------------------
#define S_TOT   13294
#define BATCH   2
#define M_TOTAL (BATCH * S_TOT)     // 26588 tokens
#define DM      256
#define DFF     1024
#define NQP     384                 // 256 offset cols + 128 attn cols

__device__ __constant__ int c_HS[4]    = {100, 50, 25, 13};
__device__ __constant__ int c_WS[4]    = {100, 50, 25, 13};
__device__ __constant__ int c_START[4] = {0, 10000, 12500, 13125};

// ---------------------------------------------------------------------------
// Scratch (no allocations allowed -> __device__ globals)
// ---------------------------------------------------------------------------
__device__ float g_value[(size_t)M_TOTAL * DM];
__device__ float g_qproj[(size_t)M_TOTAL * NQP];
__device__ float g_attn [(size_t)M_TOTAL * DM];
__device__ float g_src2 [(size_t)M_TOTAL * DM];
__device__ float g_x    [(size_t)M_TOTAL * DM];
__device__ float g_hbuf [(size_t)M_TOTAL * DFF];
__device__ float g_fbuf [(size_t)M_TOTAL * DM];
__device__ float g_wcat [DM * NQP];
__device__ float g_bcat [NQP];

// ---------------------------------------------------------------------------
// Concatenate W_off | W_attn into one (256 x 384) weight + bias
// ---------------------------------------------------------------------------
__global__ void concat_kernel(const float* __restrict__ Woff, const float* __restrict__ boff,
                              const float* __restrict__ Wattn, const float* __restrict__ battn)
{
    int idx = blockIdx.x * blockDim.x + threadIdx.x;
    if (idx < DM * NQP) {
        int k = idx / NQP, c = idx - k * NQP;
        g_wcat[idx] = (c < 256) ? Woff[k * 256 + c] : Wattn[k * 128 + (c - 256)];
    }
    if (idx < NQP) {
        g_bcat[idx] = (idx < 256) ? boff[idx] : battn[idx - 256];
    }
}

// ---------------------------------------------------------------------------
// SGEMM: C[M,N] = act(A@W + bias), optional A := A + A2 fused on load.
// BM=BN=128, BK=8, 256 threads, 8x8 per thread, warp-tiled 64x32.
// Double-buffered smem pipeline; inner product via packed fma.rn.f32x2
// (FFMA2: 2 fp32 FMAs per instruction, exact fp32 semantics).
// ---------------------------------------------------------------------------
union F32x2 {
    unsigned long long u;
    float2 f;
};

template<bool RELU, bool ADD2>
__global__ __launch_bounds__(256, 2)
void sgemm_kernel(const float* __restrict__ A, const float* __restrict__ A2,
                  const float* __restrict__ W, const float* __restrict__ bias,
                  float* __restrict__ C, int M, int N, int K)
{
    __shared__ __align__(16) float As[2][8][128];
    __shared__ __align__(16) float Ws[2][8][128];

    const int bm  = blockIdx.y * 128;
    const int bn  = blockIdx.x * 128;
    const int tid = threadIdx.x;
    const int w    = tid >> 5;
    const int lane = tid & 31;
    const int tr = ((w & 1) << 6) + ((lane >> 2) << 3);
    const int tc = ((w >> 1) << 5) + ((lane & 3) << 3);

    const int arow = tid >> 1;
    const int acol = (tid & 1) << 2;
    const int wrow = tid >> 5;
    const int wcol = (tid & 31) << 2;

    // 8 rows x 4 packed f32x2 column-pairs
    unsigned long long accp[8][4];
    #pragma unroll
    for (int i = 0; i < 8; i++)
        #pragma unroll
        for (int j = 0; j < 4; j++) accp[i][j] = 0ULL;   // (0.0f, 0.0f)

    const bool avalid = (bm + arow) < M;
    const float* Aptr  = A  + (size_t)(bm + arow) * K + acol;
    const float* A2ptr = A2 + (size_t)(bm + arow) * K + acol;
    const float* Wptr  = W  + (size_t)wrow * N + bn + wcol;

    const int nk = K >> 3;

    {
        float4 a4 = make_float4(0.f, 0.f, 0.f, 0.f);
        if (avalid) {
            a4 = *(const float4*)(Aptr);
            if (ADD2) {
                float4 b4 = *(const float4*)(A2ptr);
                a4.x += b4.x; a4.y += b4.y; a4.z += b4.z; a4.w += b4.w;
            }
        }
        As[0][acol + 0][arow] = a4.x;
        As[0][acol + 1][arow] = a4.y;
        As[0][acol + 2][arow] = a4.z;
        As[0][acol + 3][arow] = a4.w;
        *(float4*)&Ws[0][wrow][wcol] = *(const float4*)(Wptr);
    }
    __syncthreads();

    int cur = 0;
    for (int k0 = 1; k0 <= nk; k0++) {
        float4 a4n = make_float4(0.f, 0.f, 0.f, 0.f);
        float4 w4n;
        const bool more = (k0 < nk);
        if (more) {
            if (avalid) {
                a4n = *(const float4*)(Aptr + k0 * 8);
                if (ADD2) {
                    float4 b4 = *(const float4*)(A2ptr + k0 * 8);
                    a4n.x += b4.x; a4n.y += b4.y; a4n.z += b4.z; a4n.w += b4.w;
                }
            }
            w4n = *(const float4*)(Wptr + (size_t)(k0 * 8) * N);
        }

        #pragma unroll
        for (int kk = 0; kk < 8; kk++) {
            float a[8];
            *(float4*)&a[0] = *(const float4*)&As[cur][kk][tr];
            *(float4*)&a[4] = *(const float4*)&As[cur][kk][tr + 4];
            // b as 4 packed 64-bit column-pairs (32B-aligned smem)
            unsigned long long bp[4];
            {
                ulonglong2 t0 = *(const ulonglong2*)&Ws[cur][kk][tc];
                ulonglong2 t1 = *(const ulonglong2*)&Ws[cur][kk][tc + 4];
                bp[0] = t0.x; bp[1] = t0.y; bp[2] = t1.x; bp[3] = t1.y;
            }
            #pragma unroll
            for (int i = 0; i < 8; i++) {
                unsigned long long aa;
                asm("mov.b64 %0, {%1, %1};" : "=l"(aa) : "r"(__float_as_uint(a[i])));
                #pragma unroll
                for (int j = 0; j < 4; j++)
                    asm("fma.rn.f32x2 %0, %1, %2, %0;"
                        : "+l"(accp[i][j]) : "l"(aa), "l"(bp[j]));
            }
        }

        if (more) {
            const int nxt = cur ^ 1;
            As[nxt][acol + 0][arow] = a4n.x;
            As[nxt][acol + 1][arow] = a4n.y;
            As[nxt][acol + 2][arow] = a4n.z;
            As[nxt][acol + 3][arow] = a4n.w;
            *(float4*)&Ws[nxt][wrow][wcol] = w4n;
            __syncthreads();
            cur = nxt;
        }
    }

    float bia[8];
    *(float4*)&bia[0] = *(const float4*)(bias + bn + tc);
    *(float4*)&bia[4] = *(const float4*)(bias + bn + tc + 4);

    #pragma unroll
    for (int i = 0; i < 8; i++) {
        int row = bm + tr + i;
        if (row < M) {
            float o[8];
            #pragma unroll
            for (int j = 0; j < 4; j++) {
                F32x2 v; v.u = accp[i][j];
                o[2 * j + 0] = v.f.x + bia[2 * j + 0];
                o[2 * j + 1] = v.f.y + bia[2 * j + 1];
            }
            if (RELU) {
                #pragma unroll
                for (int j = 0; j < 8; j++) o[j] = fmaxf(o[j], 0.f);
            }
            *(float4*)(C + (size_t)row * N + bn + tc)     = *(float4*)&o[0];
            *(float4*)(C + (size_t)row * N + bn + tc + 4) = *(float4*)&o[4];
        }
    }
}

// ---------------------------------------------------------------------------
// MS deformable attention sampling (warp-cooperative).
// grid = M_TOTAL blocks, block = (32, 8): warp per head, lane per channel.
// ---------------------------------------------------------------------------
__global__ __launch_bounds__(256)
void msda_kernel(const float* __restrict__ refp)
{
    __shared__ float4 s_w[8][16];
    __shared__ int4   s_o[8][16];

    const int m    = blockIdx.x;
    const int h    = threadIdx.y;
    const int lane = threadIdx.x;
    const int n    = m / S_TOT;

    const float* qp = g_qproj + (size_t)m * NQP;

    float lg = (lane < 16) ? qp[256 + h * 16 + lane] : -1e30f;
    float mx = lg;
    #pragma unroll
    for (int o = 8; o > 0; o >>= 1) mx = fmaxf(mx, __shfl_xor_sync(0xffffffffu, mx, o));
    float e = __expf(lg - mx);
    float s = e;
    #pragma unroll
    for (int o = 8; o > 0; o >>= 1) s += __shfl_xor_sync(0xffffffffu, s, o);
    const float aw = e / s;

    if (lane < 16) {
        const int l  = lane >> 2;          // level
        const int Hl = c_HS[l], Wl = c_WS[l], st = c_START[l];

        const float2 off2 = *(const float2*)(qp + h * 32 + lane * 2);
        const float x = refp[(size_t)m * 8 + l * 2 + 0] * (float)Wl - 0.5f + off2.x;
        const float y = refp[(size_t)m * 8 + l * 2 + 1] * (float)Hl - 0.5f + off2.y;

        const float xf = floorf(x), yf = floorf(y);
        const int x0 = (int)xf, y0 = (int)yf;
        const int x1 = x0 + 1, y1 = y0 + 1;
        const float wx1 = x - xf, wy1 = y - yf;
        const float wx0 = 1.f - wx1, wy0 = 1.f - wy1;

        const bool vx0 = (x0 >= 0) & (x0 < Wl);
        const bool vx1 = (x1 >= 0) & (x1 < Wl);
        const bool vy0 = (y0 >= 0) & (y0 < Hl);
        const bool vy1 = (y1 >= 0) & (y1 < Hl);

        float4 w4;
        int4   o4;
        const bool v00 = vy0 & vx0, v01 = vy0 & vx1, v10 = vy1 & vx0, v11 = vy1 & vx1;
        w4.x = v00 ? wy0 * wx0 * aw : 0.f;
        w4.y = v01 ? wy0 * wx1 * aw : 0.f;
        w4.z = v10 ? wy1 * wx0 * aw : 0.f;
        w4.w = v11 ? wy1 * wx1 * aw : 0.f;
        o4.x = v00 ? (st + y0 * Wl + x0) * DM : 0;
        o4.y = v01 ? (st + y0 * Wl + x1) * DM : 0;
        o4.z = v10 ? (st + y1 * Wl + x0) * DM : 0;
        o4.w = v11 ? (st + y1 * Wl + x1) * DM : 0;

        s_w[h][lane] = w4;
        s_o[h][lane] = o4;
    }
    __syncwarp();

    const float* vb = g_value + (size_t)n * S_TOT * DM + h * 32 + lane;
    float acc = 0.f;
    #pragma unroll
    for (int p = 0; p < 16; p++) {
        const float4 w4 = s_w[h][p];
        const int4   o4 = s_o[h][p];
        acc += __ldg(vb + o4.x) * w4.x;
        acc += __ldg(vb + o4.y) * w4.y;
        acc += __ldg(vb + o4.z) * w4.z;
        acc += __ldg(vb + o4.w) * w4.w;
    }
    g_attn[(size_t)m * DM + h * 32 + lane] = acc;
}

// ---------------------------------------------------------------------------
// LayerNorm(a + b) over 256 cols; warp per row, 8 rows per block.
// ---------------------------------------------------------------------------
__global__ void ln_kernel(const float* __restrict__ a, const float* __restrict__ b,
                          const float* __restrict__ gam, const float* __restrict__ bet,
                          float* __restrict__ out)
{
    const int row = blockIdx.x * blockDim.y + threadIdx.y;
    if (row >= M_TOTAL) return;
    const int lane = threadIdx.x;
    const float* ap = a + (size_t)row * DM;
    const float* bp = b + (size_t)row * DM;

    float v[8];
    float s = 0.f;
    #pragma unroll
    for (int i = 0; i < 8; i++) {
        int c = i * 32 + lane;
        v[i] = ap[c] + bp[c];
        s += v[i];
    }
    #pragma unroll
    for (int o = 16; o > 0; o >>= 1) s += __shfl_xor_sync(0xffffffffu, s, o);
    const float mean = s * (1.0f / 256.0f);

    float var = 0.f;
    #pragma unroll
    for (int i = 0; i < 8; i++) { float d = v[i] - mean; var += d * d; }
    #pragma unroll
    for (int o = 16; o > 0; o >>= 1) var += __shfl_xor_sync(0xffffffffu, var, o);
    var *= (1.0f / 256.0f);
    const float r = rsqrtf(var + 1e-5f);

    float* op = out + (size_t)row * DM;
    #pragma unroll
    for (int i = 0; i < 8; i++) {
        int c = i * 32 + lane;
        op[c] = (v[i] - mean) * r * gam[c] + bet[c];
    }
}

// ---------------------------------------------------------------------------
// Launch
// ---------------------------------------------------------------------------
extern "C" void kernel_launch(void* const* d_in, const int* in_sizes, int n_in,
                              void* d_out, int out_size)
{
    const float* src   = (const float*)d_in[0];
    const float* pos   = (const float*)d_in[1];
    const float* refp  = (const float*)d_in[2];
    const float* W_off = (const float*)d_in[5];
    const float* b_off = (const float*)d_in[6];
    const float* W_att = (const float*)d_in[7];
    const float* b_att = (const float*)d_in[8];
    const float* W_val = (const float*)d_in[9];
    const float* b_val = (const float*)d_in[10];
    const float* W_out = (const float*)d_in[11];
    const float* b_out = (const float*)d_in[12];
    const float* W1    = (const float*)d_in[13];
    const float* b1    = (const float*)d_in[14];
    const float* W2    = (const float*)d_in[15];
    const float* b2    = (const float*)d_in[16];
    const float* g1    = (const float*)d_in[17];
    const float* be1   = (const float*)d_in[18];
    const float* g2    = (const float*)d_in[19];
    const float* be2   = (const float*)d_in[20];

    float *p_value, *p_qproj, *p_attn, *p_src2, *p_x, *p_h, *p_f, *p_wcat, *p_bcat;
    cudaGetSymbolAddress((void**)&p_value, g_value);
    cudaGetSymbolAddress((void**)&p_qproj, g_qproj);
    cudaGetSymbolAddress((void**)&p_attn,  g_attn);
    cudaGetSymbolAddress((void**)&p_src2,  g_src2);
    cudaGetSymbolAddress((void**)&p_x,     g_x);
    cudaGetSymbolAddress((void**)&p_h,     g_hbuf);
    cudaGetSymbolAddress((void**)&p_f,     g_fbuf);
    cudaGetSymbolAddress((void**)&p_wcat,  g_wcat);
    cudaGetSymbolAddress((void**)&p_bcat,  g_bcat);

    const int MB = (M_TOTAL + 127) / 128;   // 208

    concat_kernel<<<(DM * NQP + 255) / 256, 256>>>(W_off, b_off, W_att, b_att);

    sgemm_kernel<false, false><<<dim3(DM / 128, MB), 256>>>(
        src, nullptr, W_val, b_val, p_value, M_TOTAL, DM, DM);

    sgemm_kernel<false, true><<<dim3(NQP / 128, MB), 256>>>(
        src, pos, p_wcat, p_bcat, p_qproj, M_TOTAL, NQP, DM);

    msda_kernel<<<M_TOTAL, dim3(32, 8)>>>(refp);

    sgemm_kernel<false, false><<<dim3(DM / 128, MB), 256>>>(
        p_attn, nullptr, W_out, b_out, p_src2, M_TOTAL, DM, DM);

    ln_kernel<<<(M_TOTAL + 7) / 8, dim3(32, 8)>>>(src, p_src2, g1, be1, p_x);

    sgemm_kernel<true, false><<<dim3(DFF / 128, MB), 256>>>(
        p_x, nullptr, W1, b1, p_h, M_TOTAL, DFF, DM);

    sgemm_kernel<false, false><<<dim3(DM / 128, MB), 256>>>(
        p_h, nullptr, W2, b2, p_f, M_TOTAL, DM, DFF);

    ln_kernel<<<(M_TOTAL + 7) / 8, dim3(32, 8)>>>(p_x, p_f, g2, be2, (float*)d_out);
}